// round 16
// baseline (speedup 1.0000x reference)
#include <cuda_runtime.h>
#include <math.h>
#include <stdint.h>

// Problem constants
#define BSZ 2
#define TT  2048
#define CC  1024
#define HH  16
#define LL  6
#define VV  32000
#define DD  64
#define FFD 4096
#define MT  (BSZ*TT)   // 4096 rows

// -------- scratch (device globals: allocation-free per harness rules) --------
__device__ float g_x [MT*CC];
__device__ float g_h [MT*CC];
__device__ float g_q [MT*CC];
__device__ float g_k [MT*CC];
__device__ float g_v [MT*CC];
__device__ float g_o [MT*CC];
__device__ float g_ff[(size_t)MT*FFD];
__device__ float g_wT[(size_t)VV*CC];   // tf32-rounded weight staging (max 32000x1024)

// ============================== helpers ==============================
__device__ __forceinline__ uint32_t f2tf32(float x) {
    uint32_t r; asm("cvt.rna.tf32.f32 %0, %1;" : "=r"(r) : "f"(x)); return r;
}
__device__ __forceinline__ float f2tf32f(float x) {
    return __uint_as_float(f2tf32(x));
}

__device__ __forceinline__ void mma_tf32(float* d, const uint32_t* a, const uint32_t* b,
                                         const float* c) {
    asm volatile(
        "mma.sync.aligned.m16n8k8.row.col.f32.tf32.tf32.f32 "
        "{%0,%1,%2,%3}, {%4,%5,%6,%7}, {%8,%9}, {%10,%11,%12,%13};"
        : "=f"(d[0]), "=f"(d[1]), "=f"(d[2]), "=f"(d[3])
        : "r"(a[0]), "r"(a[1]), "r"(a[2]), "r"(a[3]),
          "r"(b[0]), "r"(b[1]),
          "f"(c[0]), "f"(c[1]), "f"(c[2]), "f"(c[3]));
}

__device__ __forceinline__ void ldmatrix_x4(uint32_t* r, uint32_t addr) {
    asm volatile("ldmatrix.sync.aligned.m8n8.x4.shared.b16 {%0,%1,%2,%3}, [%4];"
                 : "=r"(r[0]), "=r"(r[1]), "=r"(r[2]), "=r"(r[3]) : "r"(addr));
}

#define CP_ASYNC16(dst, src) \
    asm volatile("cp.async.cg.shared.global [%0], [%1], 16;" :: "r"(dst), "l"(src) : "memory")
#define CP_COMMIT() asm volatile("cp.async.commit_group;" ::: "memory")
#define CP_WAIT2()  asm volatile("cp.async.wait_group 2;" ::: "memory")

// ============================== tf32 rounding (weights) ==============================
__global__ void round_tf32_kernel(const float* __restrict__ in, float* __restrict__ out) {
    size_t i = ((size_t)blockIdx.x * 256 + threadIdx.x) * 4;
    float4 v = *(const float4*)(in + i);
    uint4 r;
    r.x = f2tf32(v.x); r.y = f2tf32(v.y); r.z = f2tf32(v.z); r.w = f2tf32(v.w);
    *(uint4*)(out + i) = r;
}

// Round wq|wk|wv (each CC*CC) into out at offsets 0 / CC*CC / 2*CC*CC — ONE launch.
#define RB_CC ((CC * CC) / 1024)
__global__ void round3_tf32_kernel(const float* __restrict__ w0,
                                   const float* __restrict__ w1,
                                   const float* __restrict__ w2,
                                   float* __restrict__ out) {
    int blk = blockIdx.x;
    int sub = blk / RB_CC;
    int loc = blk - sub * RB_CC;
    const float* in = (sub == 0) ? w0 : (sub == 1) ? w1 : w2;
    size_t i = ((size_t)loc * 256 + threadIdx.x) * 4;
    float4 v = *(const float4*)(in + i);
    uint4 r;
    r.x = f2tf32(v.x); r.y = f2tf32(v.y); r.z = f2tf32(v.z); r.w = f2tf32(v.w);
    *(uint4*)(out + (size_t)sub * CC * CC + i) = r;
}

// ============================== embedding ==============================
__global__ void embed_kernel(const int* __restrict__ src,
                             const float* __restrict__ emb,
                             const float* __restrict__ pos,
                             float* __restrict__ out) {
    int row = blockIdx.x;
    int tok = src[row];
    int t   = row & (TT - 1);
    float4 e = ((const float4*)(emb + (size_t)tok * CC))[threadIdx.x];
    float4 p = ((const float4*)(pos + (size_t)t * CC))[threadIdx.x];
    float4 r;
    r.x = e.x + p.x; r.y = e.y + p.y; r.z = e.z + p.z; r.w = e.w + p.w;
    ((float4*)(out + (size_t)row * CC))[threadIdx.x] = r;
}

// ============================== layernorm (tf32-rounded output) ==============================
__global__ void ln_kernel(const float* __restrict__ x,
                          const float* __restrict__ w,
                          const float* __restrict__ b,
                          float* __restrict__ out) {
    int row = blockIdx.x;
    int tid = threadIdx.x;
    __shared__ float red[8];
    __shared__ float sval;

    float4 v = ((const float4*)(x + (size_t)row * CC))[tid];
    float s = v.x + v.y + v.z + v.w;
    #pragma unroll
    for (int o = 16; o; o >>= 1) s += __shfl_xor_sync(0xffffffffu, s, o);
    if ((tid & 31) == 0) red[tid >> 5] = s;
    __syncthreads();
    if (tid == 0) {
        float t = 0.f;
        #pragma unroll
        for (int i = 0; i < 8; i++) t += red[i];
        sval = t * (1.0f / CC);
    }
    __syncthreads();
    float mu = sval;
    float dx = v.x - mu, dy = v.y - mu, dz = v.z - mu, dw = v.w - mu;
    float ss = dx*dx + dy*dy + dz*dz + dw*dw;
    #pragma unroll
    for (int o = 16; o; o >>= 1) ss += __shfl_xor_sync(0xffffffffu, ss, o);
    if ((tid & 31) == 0) red[tid >> 5] = ss;
    __syncthreads();
    if (tid == 0) {
        float t = 0.f;
        #pragma unroll
        for (int i = 0; i < 8; i++) t += red[i];
        sval = rsqrtf(t * (1.0f / CC) + 1e-5f);
    }
    __syncthreads();
    float inv = sval;
    float4 w4 = ((const float4*)w)[tid];
    float4 b4 = ((const float4*)b)[tid];
    float4 r;
    r.x = f2tf32f(dx * inv * w4.x + b4.x);
    r.y = f2tf32f(dy * inv * w4.y + b4.y);
    r.z = f2tf32f(dz * inv * w4.z + b4.z);
    r.w = f2tf32f(dw * inv * w4.w + b4.w);
    ((float4*)(out + (size_t)row * CC))[tid] = r;
}

// ============================== GEMM tile core (shared by both GEMM kernels) ==============================
#define GBM 128
#define GBN 128
#define GBK 16
#define APITCH 20
#define BPITCH 136
#define ASTAGE (GBM * APITCH * 4)        // 10240 B
#define BSTAGE (GBK * BPITCH * 4)        // 8704 B
#define NSTAGES 4
#define GEMM_SMEM (NSTAGES * (ASTAGE + BSTAGE))   // 75776 B

// Computes a 128x128 tile: acc = A[m0:,:K] @ W[:, n0:] with the R6-proven pipeline.
__device__ __forceinline__ void gemm_tile_core(
    const float* __restrict__ A, const float* __restrict__ W,
    int m0, int n0, int N, int K,
    char* smch, uint32_t smemu,
    int tid, float acc[4][4][4])
{
    int lane = tid & 31;
    int wid  = tid >> 5;
    int wm   = (wid >> 2) * 64;
    int wn   = (wid & 3) * 32;

    int lq = lane >> 2;
    int lr = lane & 3;
    (void)lq; (void)lr;

    int lrow = (lane & 7) + ((lane >> 3) & 1) * 8;
    int lcol = (lane >> 4) * 4;

    int arow = tid >> 1, ac0 = (tid & 1);
    int brow = tid >> 5, bc = tid & 31;

    const float* Asrc0 = A + (size_t)(m0 + arow) * K + ac0 * 4;
    const float* Asrc1 = A + (size_t)(m0 + arow) * K + (ac0 + 2) * 4;
    const float* Bsrc0 = W + (size_t)brow * N + n0 + bc * 4;
    const float* Bsrc1 = W + (size_t)(brow + 8) * N + n0 + bc * 4;

    uint32_t adst0 = smemu + arow * (APITCH * 4) + ac0 * 16;
    uint32_t adst1 = adst0 + 32;
    uint32_t bbase = smemu + NSTAGES * ASTAGE;
    uint32_t bdst0 = bbase + brow * (BPITCH * 4) + bc * 16;
    uint32_t bdst1 = bdst0 + 8 * (BPITCH * 4);

    const int NC = K / GBK;

    #pragma unroll
    for (int s = 0; s < NSTAGES - 1; s++) {
        size_t ko = (size_t)s * GBK;
        CP_ASYNC16(adst0 + s * ASTAGE, Asrc0 + ko);
        CP_ASYNC16(adst1 + s * ASTAGE, Asrc1 + ko);
        CP_ASYNC16(bdst0 + s * BSTAGE, Bsrc0 + ko * N);
        CP_ASYNC16(bdst1 + s * BSTAGE, Bsrc1 + ko * N);
        CP_COMMIT();
    }

    for (int c = 0; c < NC; c++) {
        CP_WAIT2();
        __syncthreads();

        int st = c & (NSTAGES - 1);
        uint32_t aST = smemu + st * ASTAGE;
        const uint32_t* BsP = (const uint32_t*)(smch + NSTAGES * ASTAGE + st * BSTAGE);

        #pragma unroll
        for (int ks = 0; ks < 2; ks++) {
            int k8 = ks * 8;
            uint32_t a[4][4], b[4][2];
            #pragma unroll
            for (int mt = 0; mt < 4; mt++) {
                uint32_t addr = aST + (((wm + mt * 16 + lrow) * APITCH) + k8 + lcol) * 4;
                ldmatrix_x4(a[mt], addr);
            }
            #pragma unroll
            for (int nt = 0; nt < 4; nt++) {
                int cn = wn + nt * 8 + (lane >> 2);
                b[nt][0] = BsP[(k8 + (lane & 3)) * BPITCH + cn];
                b[nt][1] = BsP[(k8 + 4 + (lane & 3)) * BPITCH + cn];
            }
            #pragma unroll
            for (int mt = 0; mt < 4; mt++)
                #pragma unroll
                for (int nt = 0; nt < 4; nt++)
                    mma_tf32(acc[mt][nt], a[mt], b[nt], acc[mt][nt]);
        }

        int nc = c + NSTAGES - 1;
        if (nc < NC) {
            int s = nc & (NSTAGES - 1);
            size_t ko = (size_t)nc * GBK;
            CP_ASYNC16(adst0 + s * ASTAGE, Asrc0 + ko);
            CP_ASYNC16(adst1 + s * ASTAGE, Asrc1 + ko);
            CP_ASYNC16(bdst0 + s * BSTAGE, Bsrc0 + ko * N);
            CP_ASYNC16(bdst1 + s * BSTAGE, Bsrc1 + ko * N);
        }
        CP_COMMIT();
    }
}

// ============================== general GEMM ==============================
__global__ void __launch_bounds__(256, 2)
mma_gemm(const float* __restrict__ A, const float* __restrict__ W,
         const float* __restrict__ bias, const float* __restrict__ res,
         float* __restrict__ out, int M, int N, int K, int do_gelu, int round_out) {
    extern __shared__ char smch[];
    uint32_t smemu = (uint32_t)__cvta_generic_to_shared(smch);

    int tid  = threadIdx.x;
    int lane = tid & 31;
    int wid  = tid >> 5;
    int wm   = (wid >> 2) * 64;
    int wn   = (wid & 3) * 32;
    int m0 = blockIdx.x * GBM, n0 = blockIdx.y * GBN;   // M fast, N slow
    int lq = lane >> 2;
    int lr = lane & 3;

    float acc[4][4][4];
    #pragma unroll
    for (int i = 0; i < 4; i++)
        #pragma unroll
        for (int j = 0; j < 4; j++)
            #pragma unroll
            for (int r = 0; r < 4; r++) acc[i][j][r] = 0.f;

    gemm_tile_core(A, W, m0, n0, N, K, smch, smemu, tid, acc);

    #pragma unroll
    for (int mt = 0; mt < 4; mt++) {
        int row0 = m0 + wm + mt * 16 + lq;
        #pragma unroll
        for (int nt = 0; nt < 4; nt++) {
            int col = n0 + wn + nt * 8 + lr * 2;
            #pragma unroll
            for (int half = 0; half < 2; half++) {
                int row = row0 + half * 8;
                float v0 = acc[mt][nt][half * 2 + 0];
                float v1 = acc[mt][nt][half * 2 + 1];
                if (bias) {
                    v0 += __ldg(bias + col);
                    v1 += __ldg(bias + col + 1);
                }
                if (do_gelu) {
                    v0 = 0.5f * v0 * (1.0f + erff(v0 * 0.70710678118654752f));
                    v1 = 0.5f * v1 * (1.0f + erff(v1 * 0.70710678118654752f));
                }
                if (res) {
                    const float2 rr = *(const float2*)(res + (size_t)row * N + col);
                    v0 += rr.x; v1 += rr.y;
                }
                if (round_out) { v0 = f2tf32f(v0); v1 = f2tf32f(v1); }
                float2 o2; o2.x = v0; o2.y = v1;
                *(float2*)(out + (size_t)row * N + col) = o2;
            }
        }
    }
}

// ============================== batched QKV GEMM (one launch for q,k,v) ==============================
// grid (MT/128, 24): blockIdx.y>>3 selects {q,k,v}; weights at g_wT + sub*CC*CC.
__global__ void __launch_bounds__(256, 2)
mma_gemm_qkv(const float* __restrict__ A, const float* __restrict__ Wall,
             const float* __restrict__ bq, const float* __restrict__ bk,
             const float* __restrict__ bv,
             float* __restrict__ oq, float* __restrict__ ok, float* __restrict__ ov) {
    extern __shared__ char smch[];
    uint32_t smemu = (uint32_t)__cvta_generic_to_shared(smch);

    int tid  = threadIdx.x;
    int lane = tid & 31;
    int wid  = tid >> 5;
    int wm   = (wid >> 2) * 64;
    int wn   = (wid & 3) * 32;
    int lq = lane >> 2;
    int lr = lane & 3;

    int sub = blockIdx.y >> 3;
    int m0 = blockIdx.x * GBM;
    int n0 = (blockIdx.y & 7) * GBN;

    const float* W    = Wall + (size_t)sub * CC * CC;
    const float* bias = (sub == 0) ? bq : (sub == 1) ? bk : bv;
    float* out        = (sub == 0) ? oq : (sub == 1) ? ok : ov;

    float acc[4][4][4];
    #pragma unroll
    for (int i = 0; i < 4; i++)
        #pragma unroll
        for (int j = 0; j < 4; j++)
            #pragma unroll
            for (int r = 0; r < 4; r++) acc[i][j][r] = 0.f;

    gemm_tile_core(A, W, m0, n0, CC, CC, smch, smemu, tid, acc);

    #pragma unroll
    for (int mt = 0; mt < 4; mt++) {
        int row0 = m0 + wm + mt * 16 + lq;
        #pragma unroll
        for (int nt = 0; nt < 4; nt++) {
            int col = n0 + wn + nt * 8 + lr * 2;
            float b0 = __ldg(bias + col);
            float b1 = __ldg(bias + col + 1);
            #pragma unroll
            for (int half = 0; half < 2; half++) {
                int row = row0 + half * 8;
                float2 o2;
                o2.x = acc[mt][nt][half * 2 + 0] + b0;
                o2.y = acc[mt][nt][half * 2 + 1] + b1;
                *(float2*)(out + (size_t)row * CC + col) = o2;
            }
        }
    }
}

// ============================== tensor-core flash attention (tf32, 128-row q-tiles) ==============================
#define VPITCH 72
#define PPITCH 72
#define ATTN_K_WORDS  (64 * 64)            // 4096
#define ATTN_V_WORDS  (64 * VPITCH)        // 4608
#define ATTN_P_WORDS  (8 * 16 * PPITCH)    // 9216
#define ATTN_SMEM ((ATTN_K_WORDS + ATTN_V_WORDS + ATTN_P_WORDS) * 4)   // 71680 B

__global__ void __launch_bounds__(256)
attn_kernel(const float* __restrict__ q, const float* __restrict__ k,
            const float* __restrict__ v, float* __restrict__ o) {
    extern __shared__ float sm[];
    float* Ks = sm;
    float* Vs = sm + ATTN_K_WORDS;
    float* Ps = sm + ATTN_K_WORDS + ATTN_V_WORDS;

    int tid  = threadIdx.x;
    int lane = tid & 31;
    int wid  = tid >> 5;          // 0..7
    int lq = lane >> 2;
    int lr = lane & 3;

    int qt0 = blockIdx.x * 128;
    int h = blockIdx.y, b = blockIdx.z;
    size_t base = ((size_t)b * TT) * CC + (size_t)h * DD;

    uint32_t qa[8][4];
    {
        const float* q0 = q + base + (size_t)(qt0 + wid * 16 + lq) * CC;
        const float* q1 = q0 + 8 * CC;
        #pragma unroll
        for (int ks = 0; ks < 8; ks++) {
            qa[ks][0] = f2tf32(q0[ks * 8 + lr] * 0.125f);
            qa[ks][1] = f2tf32(q1[ks * 8 + lr] * 0.125f);
            qa[ks][2] = f2tf32(q0[ks * 8 + 4 + lr] * 0.125f);
            qa[ks][3] = f2tf32(q1[ks * 8 + 4 + lr] * 0.125f);
        }
    }

    float m0r = -1e30f, m1r = -1e30f, l0r = 0.f, l1r = 0.f;
    float accO[8][4];
    #pragma unroll
    for (int nt = 0; nt < 8; nt++)
        #pragma unroll
        for (int j = 0; j < 4; j++) accO[nt][j] = 0.f;

    float* Pw = Ps + wid * 16 * PPITCH;

    for (int s0 = 0; s0 < TT; s0 += 64) {
        __syncthreads();
        #pragma unroll
        for (int i = 0; i < 4; i++) {
            int idx4 = tid + i * 256;
            int r = idx4 >> 4, d4 = idx4 & 15;
            float4 kv = *(const float4*)(k + base + (size_t)(s0 + r) * CC + d4 * 4);
            int sw = r ^ (d4 & 7);
            Ks[(d4 * 4 + 0) * 64 + (sw ^ 0 )] = __uint_as_float(f2tf32(kv.x));
            Ks[(d4 * 4 + 1) * 64 + (sw ^ 8 )] = __uint_as_float(f2tf32(kv.y));
            Ks[(d4 * 4 + 2) * 64 + (sw ^ 16)] = __uint_as_float(f2tf32(kv.z));
            Ks[(d4 * 4 + 3) * 64 + (sw ^ 24)] = __uint_as_float(f2tf32(kv.w));

            float4 vv = *(const float4*)(v + base + (size_t)(s0 + r) * CC + d4 * 4);
            float* vp = &Vs[r * VPITCH + d4 * 4];
            vp[0] = f2tf32f(vv.x); vp[1] = f2tf32f(vv.y);
            vp[2] = f2tf32f(vv.z); vp[3] = f2tf32f(vv.w);
        }
        __syncthreads();

        float sacc[8][4];
        #pragma unroll
        for (int nt = 0; nt < 8; nt++)
            #pragma unroll
            for (int j = 0; j < 4; j++) sacc[nt][j] = 0.f;

        #pragma unroll
        for (int ks = 0; ks < 8; ks++) {
            int d0 = ks * 8 + lr;
            int d1 = d0 + 4;
            int sw0 = (lr << 3) ^ ((2 * ks) & 7);
            int sw1 = (lr << 3) ^ ((2 * ks + 1) & 7);
            #pragma unroll
            for (int nt = 0; nt < 8; nt++) {
                uint32_t bfr[2];
                bfr[0] = __float_as_uint(Ks[d0 * 64 + ((nt * 8 + lq) ^ sw0)]);
                bfr[1] = __float_as_uint(Ks[d1 * 64 + ((nt * 8 + lq) ^ sw1)]);
                mma_tf32(sacc[nt], qa[ks], bfr, sacc[nt]);
            }
        }

        float tm0 = -1e30f, tm1 = -1e30f;
        #pragma unroll
        for (int nt = 0; nt < 8; nt++) {
            tm0 = fmaxf(tm0, fmaxf(sacc[nt][0], sacc[nt][1]));
            tm1 = fmaxf(tm1, fmaxf(sacc[nt][2], sacc[nt][3]));
        }
        tm0 = fmaxf(tm0, __shfl_xor_sync(0xffffffffu, tm0, 1));
        tm0 = fmaxf(tm0, __shfl_xor_sync(0xffffffffu, tm0, 2));
        tm1 = fmaxf(tm1, __shfl_xor_sync(0xffffffffu, tm1, 1));
        tm1 = fmaxf(tm1, __shfl_xor_sync(0xffffffffu, tm1, 2));

        float mn0 = fmaxf(m0r, tm0);
        float mn1 = fmaxf(m1r, tm1);
        float cr0 = __expf(m0r - mn0);
        float cr1 = __expf(m1r - mn1);
        m0r = mn0; m1r = mn1;

        float rs0 = 0.f, rs1 = 0.f;
        #pragma unroll
        for (int nt = 0; nt < 8; nt++) {
            sacc[nt][0] = __expf(sacc[nt][0] - mn0);
            sacc[nt][1] = __expf(sacc[nt][1] - mn0);
            sacc[nt][2] = __expf(sacc[nt][2] - mn1);
            sacc[nt][3] = __expf(sacc[nt][3] - mn1);
            rs0 += sacc[nt][0] + sacc[nt][1];
            rs1 += sacc[nt][2] + sacc[nt][3];
        }
        rs0 += __shfl_xor_sync(0xffffffffu, rs0, 1);
        rs0 += __shfl_xor_sync(0xffffffffu, rs0, 2);
        rs1 += __shfl_xor_sync(0xffffffffu, rs1, 1);
        rs1 += __shfl_xor_sync(0xffffffffu, rs1, 2);
        l0r = l0r * cr0 + rs0;
        l1r = l1r * cr1 + rs1;

        #pragma unroll
        for (int nt = 0; nt < 8; nt++) {
            accO[nt][0] *= cr0; accO[nt][1] *= cr0;
            accO[nt][2] *= cr1; accO[nt][3] *= cr1;
        }

        __syncwarp();
        #pragma unroll
        for (int nt = 0; nt < 8; nt++) {
            float2 p01; p01.x = f2tf32f(sacc[nt][0]); p01.y = f2tf32f(sacc[nt][1]);
            float2 p23; p23.x = f2tf32f(sacc[nt][2]); p23.y = f2tf32f(sacc[nt][3]);
            *(float2*)&Pw[lq * PPITCH + nt * 8 + 2 * lr]       = p01;
            *(float2*)&Pw[(lq + 8) * PPITCH + nt * 8 + 2 * lr] = p23;
        }
        __syncwarp();

        #pragma unroll
        for (int ks = 0; ks < 8; ks++) {
            uint32_t pa[4];
            pa[0] = __float_as_uint(Pw[lq * PPITCH + ks * 8 + lr]);
            pa[1] = __float_as_uint(Pw[(lq + 8) * PPITCH + ks * 8 + lr]);
            pa[2] = __float_as_uint(Pw[lq * PPITCH + ks * 8 + 4 + lr]);
            pa[3] = __float_as_uint(Pw[(lq + 8) * PPITCH + ks * 8 + 4 + lr]);
            #pragma unroll
            for (int nt = 0; nt < 8; nt++) {
                uint32_t bfr[2];
                bfr[0] = __float_as_uint(Vs[(ks * 8 + lr) * VPITCH + nt * 8 + lq]);
                bfr[1] = __float_as_uint(Vs[(ks * 8 + 4 + lr) * VPITCH + nt * 8 + lq]);
                mma_tf32(accO[nt], pa, bfr, accO[nt]);
            }
        }
    }

    float inv0 = 1.0f / l0r, inv1 = 1.0f / l1r;
    int row0 = qt0 + wid * 16 + lq;
    #pragma unroll
    for (int nt = 0; nt < 8; nt++) {
        float2 o0, o1;
        o0.x = f2tf32f(accO[nt][0] * inv0); o0.y = f2tf32f(accO[nt][1] * inv0);
        o1.x = f2tf32f(accO[nt][2] * inv1); o1.y = f2tf32f(accO[nt][3] * inv1);
        *(float2*)(o + base + (size_t)row0 * CC + nt * 8 + 2 * lr)       = o0;
        *(float2*)(o + base + (size_t)(row0 + 8) * CC + nt * 8 + 2 * lr) = o1;
    }
}

// ============================== launcher ==============================
extern "C" void kernel_launch(void* const* d_in, const int* in_sizes, int n_in,
                              void* d_out, int out_size) {
    (void)in_sizes; (void)n_in; (void)out_size;

    const int*   src     = (const int*)  d_in[0];
    const float* src_emb = (const float*)d_in[1];
    const float* pos_emb = (const float*)d_in[2];
    const float* ln1_w   = (const float*)d_in[3];
    const float* ln1_b   = (const float*)d_in[4];
    const float* wq      = (const float*)d_in[5];
    const float* bq      = (const float*)d_in[6];
    const float* wk      = (const float*)d_in[7];
    const float* bk      = (const float*)d_in[8];
    const float* wv      = (const float*)d_in[9];
    const float* bv      = (const float*)d_in[10];
    const float* wo      = (const float*)d_in[11];
    const float* bo      = (const float*)d_in[12];
    const float* ln2_w   = (const float*)d_in[13];
    const float* ln2_b   = (const float*)d_in[14];
    const float* w1      = (const float*)d_in[15];
    const float* b1      = (const float*)d_in[16];
    const float* w2      = (const float*)d_in[17];
    const float* b2      = (const float*)d_in[18];
    const float* lnf_w   = (const float*)d_in[19];
    const float* lnf_b   = (const float*)d_in[20];
    const float* head_w  = (const float*)d_in[21];

    float *xb, *hb, *qb, *kb, *vb, *ob, *fb, *wT;
    cudaGetSymbolAddress((void**)&xb, g_x);
    cudaGetSymbolAddress((void**)&hb, g_h);
    cudaGetSymbolAddress((void**)&qb, g_q);
    cudaGetSymbolAddress((void**)&kb, g_k);
    cudaGetSymbolAddress((void**)&vb, g_v);
    cudaGetSymbolAddress((void**)&ob, g_o);
    cudaGetSymbolAddress((void**)&fb, g_ff);
    cudaGetSymbolAddress((void**)&wT, g_wT);

    cudaFuncSetAttribute(attn_kernel, cudaFuncAttributeMaxDynamicSharedMemorySize, ATTN_SMEM);
    cudaFuncSetAttribute(mma_gemm, cudaFuncAttributeMaxDynamicSharedMemorySize, GEMM_SMEM);
    cudaFuncSetAttribute(mma_gemm_qkv, cudaFuncAttributeMaxDynamicSharedMemorySize, GEMM_SMEM);

    embed_kernel<<<MT, 256>>>(src, src_emb, pos_emb, xb);

    // grids: x = M tiles (fast), y = N tiles (slow)
    dim3 gC(MT / GBM, CC / GBN);      // (32, 8)
    dim3 gQKV(MT / GBM, 3 * CC / GBN);// (32, 24)
    dim3 gF(MT / GBM, FFD / GBN);     // (32, 32)
    dim3 gH(MT / GBM, VV / GBN);      // (32, 250)
    dim3 gA(TT / 128, HH, BSZ);       // (16, 16, 2)

    const int RB_FF = (CC * FFD) / 1024;
    const int RB_HD = (VV * CC) / 1024;

    for (int l = 0; l < LL; l++) {
        size_t wOff  = (size_t)l * CC * CC;
        size_t w1Off = (size_t)l * CC * FFD;
        size_t w2Off = (size_t)l * FFD * CC;

        ln_kernel<<<MT, 256>>>(xb, ln1_w + l * CC, ln1_b + l * CC, hb);

        round3_tf32_kernel<<<3 * RB_CC, 256>>>(wq + wOff, wk + wOff, wv + wOff, wT);
        mma_gemm_qkv<<<gQKV, 256, GEMM_SMEM>>>(hb, wT, bq + l * CC, bk + l * CC,
                                               bv + l * CC, qb, kb, vb);

        attn_kernel<<<gA, 256, ATTN_SMEM>>>(qb, kb, vb, ob);

        round_tf32_kernel<<<RB_CC, 256>>>(wo + wOff, wT);
        mma_gemm<<<gC, 256, GEMM_SMEM>>>(ob, wT, bo + l * CC, xb, xb, MT, CC, CC, 0, 0);

        ln_kernel<<<MT, 256>>>(xb, ln2_w + l * CC, ln2_b + l * CC, hb);

        round_tf32_kernel<<<RB_FF, 256>>>(w1 + w1Off, wT);
        mma_gemm<<<gF, 256, GEMM_SMEM>>>(hb, wT, b1 + l * FFD, nullptr, fb, MT, FFD, CC, 1, 1);
        round_tf32_kernel<<<RB_FF, 256>>>(w2 + w2Off, wT);
        mma_gemm<<<gC, 256, GEMM_SMEM>>>(fb, wT, b2 + l * CC, xb, xb, MT, CC, FFD, 0, 0);
    }

    ln_kernel<<<MT, 256>>>(xb, lnf_w, lnf_b, hb);
    round_tf32_kernel<<<RB_HD, 256>>>(head_w, wT);
    mma_gemm<<<gH, 256, GEMM_SMEM>>>(hb, wT, nullptr, nullptr, (float*)d_out, MT, VV, CC, 0, 0);
}

// round 17
// speedup vs baseline: 1.0250x; 1.0250x over previous
#include <cuda_runtime.h>
#include <math.h>
#include <stdint.h>

// Problem constants
#define BSZ 2
#define TT  2048
#define CC  1024
#define HH  16
#define LL  6
#define VV  32000
#define DD  64
#define FFD 4096
#define MT  (BSZ*TT)   // 4096 rows

// -------- scratch (device globals: allocation-free per harness rules) --------
__device__ float g_x [MT*CC];
__device__ float g_h [MT*CC];
__device__ float g_q [MT*CC];
__device__ float g_k [MT*CC];
__device__ float g_v [MT*CC];
__device__ float g_o [MT*CC];
__device__ float g_ff[(size_t)MT*FFD];
__device__ float g_wT[(size_t)VV*CC];   // tf32-rounded weight staging (max 32000x1024)

// ============================== helpers ==============================
__device__ __forceinline__ uint32_t f2tf32(float x) {
    uint32_t r; asm("cvt.rna.tf32.f32 %0, %1;" : "=r"(r) : "f"(x)); return r;
}
__device__ __forceinline__ float f2tf32f(float x) {
    return __uint_as_float(f2tf32(x));
}

__device__ __forceinline__ void mma_tf32(float* d, const uint32_t* a, const uint32_t* b,
                                         const float* c) {
    asm volatile(
        "mma.sync.aligned.m16n8k8.row.col.f32.tf32.tf32.f32 "
        "{%0,%1,%2,%3}, {%4,%5,%6,%7}, {%8,%9}, {%10,%11,%12,%13};"
        : "=f"(d[0]), "=f"(d[1]), "=f"(d[2]), "=f"(d[3])
        : "r"(a[0]), "r"(a[1]), "r"(a[2]), "r"(a[3]),
          "r"(b[0]), "r"(b[1]),
          "f"(c[0]), "f"(c[1]), "f"(c[2]), "f"(c[3]));
}

__device__ __forceinline__ void ldmatrix_x4(uint32_t* r, uint32_t addr) {
    asm volatile("ldmatrix.sync.aligned.m8n8.x4.shared.b16 {%0,%1,%2,%3}, [%4];"
                 : "=r"(r[0]), "=r"(r[1]), "=r"(r[2]), "=r"(r[3]) : "r"(addr));
}

#define CP_ASYNC16(dst, src) \
    asm volatile("cp.async.cg.shared.global [%0], [%1], 16;" :: "r"(dst), "l"(src) : "memory")
#define CP_COMMIT() asm volatile("cp.async.commit_group;" ::: "memory")
#define CP_WAIT2()  asm volatile("cp.async.wait_group 2;" ::: "memory")

// ============================== tf32 rounding (weights) ==============================
__global__ void round_tf32_kernel(const float* __restrict__ in, float* __restrict__ out) {
    size_t i = ((size_t)blockIdx.x * 256 + threadIdx.x) * 4;
    float4 v = *(const float4*)(in + i);
    uint4 r;
    r.x = f2tf32(v.x); r.y = f2tf32(v.y); r.z = f2tf32(v.z); r.w = f2tf32(v.w);
    *(uint4*)(out + i) = r;
}

// ============================== embedding ==============================
__global__ void embed_kernel(const int* __restrict__ src,
                             const float* __restrict__ emb,
                             const float* __restrict__ pos,
                             float* __restrict__ out) {
    int row = blockIdx.x;
    int tok = src[row];
    int t   = row & (TT - 1);
    float4 e = ((const float4*)(emb + (size_t)tok * CC))[threadIdx.x];
    float4 p = ((const float4*)(pos + (size_t)t * CC))[threadIdx.x];
    float4 r;
    r.x = e.x + p.x; r.y = e.y + p.y; r.z = e.z + p.z; r.w = e.w + p.w;
    ((float4*)(out + (size_t)row * CC))[threadIdx.x] = r;
}

// ============================== layernorm (tf32-rounded output) ==============================
__global__ void ln_kernel(const float* __restrict__ x,
                          const float* __restrict__ w,
                          const float* __restrict__ b,
                          float* __restrict__ out) {
    int row = blockIdx.x;
    int tid = threadIdx.x;
    __shared__ float red[8];
    __shared__ float sval;

    float4 v = ((const float4*)(x + (size_t)row * CC))[tid];
    float s = v.x + v.y + v.z + v.w;
    #pragma unroll
    for (int o = 16; o; o >>= 1) s += __shfl_xor_sync(0xffffffffu, s, o);
    if ((tid & 31) == 0) red[tid >> 5] = s;
    __syncthreads();
    if (tid == 0) {
        float t = 0.f;
        #pragma unroll
        for (int i = 0; i < 8; i++) t += red[i];
        sval = t * (1.0f / CC);
    }
    __syncthreads();
    float mu = sval;
    float dx = v.x - mu, dy = v.y - mu, dz = v.z - mu, dw = v.w - mu;
    float ss = dx*dx + dy*dy + dz*dz + dw*dw;
    #pragma unroll
    for (int o = 16; o; o >>= 1) ss += __shfl_xor_sync(0xffffffffu, ss, o);
    if ((tid & 31) == 0) red[tid >> 5] = ss;
    __syncthreads();
    if (tid == 0) {
        float t = 0.f;
        #pragma unroll
        for (int i = 0; i < 8; i++) t += red[i];
        sval = rsqrtf(t * (1.0f / CC) + 1e-5f);
    }
    __syncthreads();
    float inv = sval;
    float4 w4 = ((const float4*)w)[tid];
    float4 b4 = ((const float4*)b)[tid];
    float4 r;
    r.x = f2tf32f(dx * inv * w4.x + b4.x);
    r.y = f2tf32f(dy * inv * w4.y + b4.y);
    r.z = f2tf32f(dz * inv * w4.z + b4.z);
    r.w = f2tf32f(dw * inv * w4.w + b4.w);
    ((float4*)(out + (size_t)row * CC))[tid] = r;
}

// ============================== tf32 tensor-core GEMM (R6/R15-proven; M on fast grid axis) ==============================
#define GBM 128
#define GBN 128
#define GBK 16
#define APITCH 20
#define BPITCH 136
#define ASTAGE (GBM * APITCH * 4)        // 10240 B
#define BSTAGE (GBK * BPITCH * 4)        // 8704 B
#define NSTAGES 4
#define GEMM_SMEM (NSTAGES * (ASTAGE + BSTAGE))   // 75776 B

__global__ void __launch_bounds__(256, 2)
mma_gemm(const float* __restrict__ A, const float* __restrict__ W,
         const float* __restrict__ bias, const float* __restrict__ res,
         float* __restrict__ out, int M, int N, int K, int do_gelu, int round_out) {
    extern __shared__ char smch[];
    uint32_t smemu = (uint32_t)__cvta_generic_to_shared(smch);

    int tid  = threadIdx.x;
    int lane = tid & 31;
    int wid  = tid >> 5;
    int wm   = (wid >> 2) * 64;
    int wn   = (wid & 3) * 32;
    int m0 = blockIdx.x * GBM, n0 = blockIdx.y * GBN;   // M fast, N slow

    int lq = lane >> 2;
    int lr = lane & 3;

    int lrow = (lane & 7) + ((lane >> 3) & 1) * 8;
    int lcol = (lane >> 4) * 4;

    int arow = tid >> 1, ac0 = (tid & 1);
    int brow = tid >> 5, bc = tid & 31;

    const float* Asrc0 = A + (size_t)(m0 + arow) * K + ac0 * 4;
    const float* Asrc1 = A + (size_t)(m0 + arow) * K + (ac0 + 2) * 4;
    const float* Bsrc0 = W + (size_t)brow * N + n0 + bc * 4;
    const float* Bsrc1 = W + (size_t)(brow + 8) * N + n0 + bc * 4;

    uint32_t adst0 = smemu + arow * (APITCH * 4) + ac0 * 16;
    uint32_t adst1 = adst0 + 32;
    uint32_t bbase = smemu + NSTAGES * ASTAGE;
    uint32_t bdst0 = bbase + brow * (BPITCH * 4) + bc * 16;
    uint32_t bdst1 = bdst0 + 8 * (BPITCH * 4);

    float acc[4][4][4];
    #pragma unroll
    for (int i = 0; i < 4; i++)
        #pragma unroll
        for (int j = 0; j < 4; j++)
            #pragma unroll
            for (int r = 0; r < 4; r++) acc[i][j][r] = 0.f;

    const int NC = K / GBK;

    #pragma unroll
    for (int s = 0; s < NSTAGES - 1; s++) {
        size_t ko = (size_t)s * GBK;
        CP_ASYNC16(adst0 + s * ASTAGE, Asrc0 + ko);
        CP_ASYNC16(adst1 + s * ASTAGE, Asrc1 + ko);
        CP_ASYNC16(bdst0 + s * BSTAGE, Bsrc0 + ko * N);
        CP_ASYNC16(bdst1 + s * BSTAGE, Bsrc1 + ko * N);
        CP_COMMIT();
    }

    for (int c = 0; c < NC; c++) {
        CP_WAIT2();
        __syncthreads();

        int st = c & (NSTAGES - 1);
        uint32_t aST = smemu + st * ASTAGE;
        const uint32_t* BsP = (const uint32_t*)(smch + NSTAGES * ASTAGE + st * BSTAGE);

        #pragma unroll
        for (int ks = 0; ks < 2; ks++) {
            int k8 = ks * 8;
            uint32_t a[4][4], b[4][2];
            #pragma unroll
            for (int mt = 0; mt < 4; mt++) {
                uint32_t addr = aST + (((wm + mt * 16 + lrow) * APITCH) + k8 + lcol) * 4;
                ldmatrix_x4(a[mt], addr);
            }
            #pragma unroll
            for (int nt = 0; nt < 4; nt++) {
                int cn = wn + nt * 8 + lq;
                b[nt][0] = BsP[(k8 + lr) * BPITCH + cn];
                b[nt][1] = BsP[(k8 + 4 + lr) * BPITCH + cn];
            }
            #pragma unroll
            for (int mt = 0; mt < 4; mt++)
                #pragma unroll
                for (int nt = 0; nt < 4; nt++)
                    mma_tf32(acc[mt][nt], a[mt], b[nt], acc[mt][nt]);
        }

        int nc = c + NSTAGES - 1;
        if (nc < NC) {
            int s = nc & (NSTAGES - 1);
            size_t ko = (size_t)nc * GBK;
            CP_ASYNC16(adst0 + s * ASTAGE, Asrc0 + ko);
            CP_ASYNC16(adst1 + s * ASTAGE, Asrc1 + ko);
            CP_ASYNC16(bdst0 + s * BSTAGE, Bsrc0 + ko * N);
            CP_ASYNC16(bdst1 + s * BSTAGE, Bsrc1 + ko * N);
        }
        CP_COMMIT();
    }

    #pragma unroll
    for (int mt = 0; mt < 4; mt++) {
        int row0 = m0 + wm + mt * 16 + lq;
        #pragma unroll
        for (int nt = 0; nt < 4; nt++) {
            int col = n0 + wn + nt * 8 + lr * 2;
            #pragma unroll
            for (int half = 0; half < 2; half++) {
                int row = row0 + half * 8;
                float v0 = acc[mt][nt][half * 2 + 0];
                float v1 = acc[mt][nt][half * 2 + 1];
                if (bias) {
                    v0 += __ldg(bias + col);
                    v1 += __ldg(bias + col + 1);
                }
                if (do_gelu) {
                    v0 = 0.5f * v0 * (1.0f + erff(v0 * 0.70710678118654752f));
                    v1 = 0.5f * v1 * (1.0f + erff(v1 * 0.70710678118654752f));
                }
                if (res) {
                    const float2 rr = *(const float2*)(res + (size_t)row * N + col);
                    v0 += rr.x; v1 += rr.y;
                }
                if (round_out) { v0 = f2tf32f(v0); v1 = f2tf32f(v1); }
                float2 o2; o2.x = v0; o2.y = v1;
                *(float2*)(out + (size_t)row * N + col) = o2;
            }
        }
    }
}

// ============================== batched QKV GEMM (standalone copy, N=K=CC) ==============================
// grid (MT/128, 24): sub = blockIdx.y>>3 selects {q,k,v}; W at Wall + sub*CC*CC.
__global__ void __launch_bounds__(256, 2)
mma_gemm_qkv(const float* __restrict__ A, const float* __restrict__ Wall,
             const float* __restrict__ bqp, const float* __restrict__ bkp,
             const float* __restrict__ bvp,
             float* __restrict__ oq, float* __restrict__ ok, float* __restrict__ ov) {
    extern __shared__ char smch[];
    uint32_t smemu = (uint32_t)__cvta_generic_to_shared(smch);

    int tid  = threadIdx.x;
    int lane = tid & 31;
    int wid  = tid >> 5;
    int wm   = (wid >> 2) * 64;
    int wn   = (wid & 3) * 32;

    int sub = blockIdx.y >> 3;
    int m0 = blockIdx.x * GBM;
    int n0 = (blockIdx.y & 7) * GBN;
    const float* W    = Wall + (size_t)sub * CC * CC;
    const float* bias = (sub == 0) ? bqp : (sub == 1) ? bkp : bvp;
    float* out        = (sub == 0) ? oq  : (sub == 1) ? ok  : ov;

    int lq = lane >> 2;
    int lr = lane & 3;

    int lrow = (lane & 7) + ((lane >> 3) & 1) * 8;
    int lcol = (lane >> 4) * 4;

    int arow = tid >> 1, ac0 = (tid & 1);
    int brow = tid >> 5, bc = tid & 31;

    const float* Asrc0 = A + (size_t)(m0 + arow) * CC + ac0 * 4;
    const float* Asrc1 = A + (size_t)(m0 + arow) * CC + (ac0 + 2) * 4;
    const float* Bsrc0 = W + (size_t)brow * CC + n0 + bc * 4;
    const float* Bsrc1 = W + (size_t)(brow + 8) * CC + n0 + bc * 4;

    uint32_t adst0 = smemu + arow * (APITCH * 4) + ac0 * 16;
    uint32_t adst1 = adst0 + 32;
    uint32_t bbase = smemu + NSTAGES * ASTAGE;
    uint32_t bdst0 = bbase + brow * (BPITCH * 4) + bc * 16;
    uint32_t bdst1 = bdst0 + 8 * (BPITCH * 4);

    float acc[4][4][4];
    #pragma unroll
    for (int i = 0; i < 4; i++)
        #pragma unroll
        for (int j = 0; j < 4; j++)
            #pragma unroll
            for (int r = 0; r < 4; r++) acc[i][j][r] = 0.f;

    const int NC = CC / GBK;

    #pragma unroll
    for (int s = 0; s < NSTAGES - 1; s++) {
        size_t ko = (size_t)s * GBK;
        CP_ASYNC16(adst0 + s * ASTAGE, Asrc0 + ko);
        CP_ASYNC16(adst1 + s * ASTAGE, Asrc1 + ko);
        CP_ASYNC16(bdst0 + s * BSTAGE, Bsrc0 + ko * CC);
        CP_ASYNC16(bdst1 + s * BSTAGE, Bsrc1 + ko * CC);
        CP_COMMIT();
    }

    for (int c = 0; c < NC; c++) {
        CP_WAIT2();
        __syncthreads();

        int st = c & (NSTAGES - 1);
        uint32_t aST = smemu + st * ASTAGE;
        const uint32_t* BsP = (const uint32_t*)(smch + NSTAGES * ASTAGE + st * BSTAGE);

        #pragma unroll
        for (int ks = 0; ks < 2; ks++) {
            int k8 = ks * 8;
            uint32_t a[4][4], b[4][2];
            #pragma unroll
            for (int mt = 0; mt < 4; mt++) {
                uint32_t addr = aST + (((wm + mt * 16 + lrow) * APITCH) + k8 + lcol) * 4;
                ldmatrix_x4(a[mt], addr);
            }
            #pragma unroll
            for (int nt = 0; nt < 4; nt++) {
                int cn = wn + nt * 8 + lq;
                b[nt][0] = BsP[(k8 + lr) * BPITCH + cn];
                b[nt][1] = BsP[(k8 + 4 + lr) * BPITCH + cn];
            }
            #pragma unroll
            for (int mt = 0; mt < 4; mt++)
                #pragma unroll
                for (int nt = 0; nt < 4; nt++)
                    mma_tf32(acc[mt][nt], a[mt], b[nt], acc[mt][nt]);
        }

        int nc = c + NSTAGES - 1;
        if (nc < NC) {
            int s = nc & (NSTAGES - 1);
            size_t ko = (size_t)nc * GBK;
            CP_ASYNC16(adst0 + s * ASTAGE, Asrc0 + ko);
            CP_ASYNC16(adst1 + s * ASTAGE, Asrc1 + ko);
            CP_ASYNC16(bdst0 + s * BSTAGE, Bsrc0 + ko * CC);
            CP_ASYNC16(bdst1 + s * BSTAGE, Bsrc1 + ko * CC);
        }
        CP_COMMIT();
    }

    #pragma unroll
    for (int mt = 0; mt < 4; mt++) {
        int row0 = m0 + wm + mt * 16 + lq;
        #pragma unroll
        for (int nt = 0; nt < 4; nt++) {
            int col = n0 + wn + nt * 8 + lr * 2;
            float b0 = __ldg(bias + col);
            float b1 = __ldg(bias + col + 1);
            #pragma unroll
            for (int half = 0; half < 2; half++) {
                int row = row0 + half * 8;
                float2 o2;
                o2.x = acc[mt][nt][half * 2 + 0] + b0;
                o2.y = acc[mt][nt][half * 2 + 1] + b1;
                *(float2*)(out + (size_t)row * CC + col) = o2;
            }
        }
    }
}

// ============================== tensor-core flash attention (tf32, 128-row q-tiles) ==============================
#define VPITCH 72
#define PPITCH 72
#define ATTN_K_WORDS  (64 * 64)            // 4096
#define ATTN_V_WORDS  (64 * VPITCH)        // 4608
#define ATTN_P_WORDS  (8 * 16 * PPITCH)    // 9216
#define ATTN_SMEM ((ATTN_K_WORDS + ATTN_V_WORDS + ATTN_P_WORDS) * 4)   // 71680 B

__global__ void __launch_bounds__(256)
attn_kernel(const float* __restrict__ q, const float* __restrict__ k,
            const float* __restrict__ v, float* __restrict__ o) {
    extern __shared__ float sm[];
    float* Ks = sm;
    float* Vs = sm + ATTN_K_WORDS;
    float* Ps = sm + ATTN_K_WORDS + ATTN_V_WORDS;

    int tid  = threadIdx.x;
    int lane = tid & 31;
    int wid  = tid >> 5;          // 0..7
    int lq = lane >> 2;
    int lr = lane & 3;

    int qt0 = blockIdx.x * 128;
    int h = blockIdx.y, b = blockIdx.z;
    size_t base = ((size_t)b * TT) * CC + (size_t)h * DD;

    uint32_t qa[8][4];
    {
        const float* q0 = q + base + (size_t)(qt0 + wid * 16 + lq) * CC;
        const float* q1 = q0 + 8 * CC;
        #pragma unroll
        for (int ks = 0; ks < 8; ks++) {
            qa[ks][0] = f2tf32(q0[ks * 8 + lr] * 0.125f);
            qa[ks][1] = f2tf32(q1[ks * 8 + lr] * 0.125f);
            qa[ks][2] = f2tf32(q0[ks * 8 + 4 + lr] * 0.125f);
            qa[ks][3] = f2tf32(q1[ks * 8 + 4 + lr] * 0.125f);
        }
    }

    float m0r = -1e30f, m1r = -1e30f, l0r = 0.f, l1r = 0.f;
    float accO[8][4];
    #pragma unroll
    for (int nt = 0; nt < 8; nt++)
        #pragma unroll
        for (int j = 0; j < 4; j++) accO[nt][j] = 0.f;

    float* Pw = Ps + wid * 16 * PPITCH;

    for (int s0 = 0; s0 < TT; s0 += 64) {
        __syncthreads();
        #pragma unroll
        for (int i = 0; i < 4; i++) {
            int idx4 = tid + i * 256;
            int r = idx4 >> 4, d4 = idx4 & 15;
            float4 kv = *(const float4*)(k + base + (size_t)(s0 + r) * CC + d4 * 4);
            int sw = r ^ (d4 & 7);
            Ks[(d4 * 4 + 0) * 64 + (sw ^ 0 )] = __uint_as_float(f2tf32(kv.x));
            Ks[(d4 * 4 + 1) * 64 + (sw ^ 8 )] = __uint_as_float(f2tf32(kv.y));
            Ks[(d4 * 4 + 2) * 64 + (sw ^ 16)] = __uint_as_float(f2tf32(kv.z));
            Ks[(d4 * 4 + 3) * 64 + (sw ^ 24)] = __uint_as_float(f2tf32(kv.w));

            float4 vv = *(const float4*)(v + base + (size_t)(s0 + r) * CC + d4 * 4);
            float* vp = &Vs[r * VPITCH + d4 * 4];
            vp[0] = f2tf32f(vv.x); vp[1] = f2tf32f(vv.y);
            vp[2] = f2tf32f(vv.z); vp[3] = f2tf32f(vv.w);
        }
        __syncthreads();

        float sacc[8][4];
        #pragma unroll
        for (int nt = 0; nt < 8; nt++)
            #pragma unroll
            for (int j = 0; j < 4; j++) sacc[nt][j] = 0.f;

        #pragma unroll
        for (int ks = 0; ks < 8; ks++) {
            int d0 = ks * 8 + lr;
            int d1 = d0 + 4;
            int sw0 = (lr << 3) ^ ((2 * ks) & 7);
            int sw1 = (lr << 3) ^ ((2 * ks + 1) & 7);
            #pragma unroll
            for (int nt = 0; nt < 8; nt++) {
                uint32_t bfr[2];
                bfr[0] = __float_as_uint(Ks[d0 * 64 + ((nt * 8 + lq) ^ sw0)]);
                bfr[1] = __float_as_uint(Ks[d1 * 64 + ((nt * 8 + lq) ^ sw1)]);
                mma_tf32(sacc[nt], qa[ks], bfr, sacc[nt]);
            }
        }

        float tm0 = -1e30f, tm1 = -1e30f;
        #pragma unroll
        for (int nt = 0; nt < 8; nt++) {
            tm0 = fmaxf(tm0, fmaxf(sacc[nt][0], sacc[nt][1]));
            tm1 = fmaxf(tm1, fmaxf(sacc[nt][2], sacc[nt][3]));
        }
        tm0 = fmaxf(tm0, __shfl_xor_sync(0xffffffffu, tm0, 1));
        tm0 = fmaxf(tm0, __shfl_xor_sync(0xffffffffu, tm0, 2));
        tm1 = fmaxf(tm1, __shfl_xor_sync(0xffffffffu, tm1, 1));
        tm1 = fmaxf(tm1, __shfl_xor_sync(0xffffffffu, tm1, 2));

        float mn0 = fmaxf(m0r, tm0);
        float mn1 = fmaxf(m1r, tm1);
        float cr0 = __expf(m0r - mn0);
        float cr1 = __expf(m1r - mn1);
        m0r = mn0; m1r = mn1;

        float rs0 = 0.f, rs1 = 0.f;
        #pragma unroll
        for (int nt = 0; nt < 8; nt++) {
            sacc[nt][0] = __expf(sacc[nt][0] - mn0);
            sacc[nt][1] = __expf(sacc[nt][1] - mn0);
            sacc[nt][2] = __expf(sacc[nt][2] - mn1);
            sacc[nt][3] = __expf(sacc[nt][3] - mn1);
            rs0 += sacc[nt][0] + sacc[nt][1];
            rs1 += sacc[nt][2] + sacc[nt][3];
        }
        rs0 += __shfl_xor_sync(0xffffffffu, rs0, 1);
        rs0 += __shfl_xor_sync(0xffffffffu, rs0, 2);
        rs1 += __shfl_xor_sync(0xffffffffu, rs1, 1);
        rs1 += __shfl_xor_sync(0xffffffffu, rs1, 2);
        l0r = l0r * cr0 + rs0;
        l1r = l1r * cr1 + rs1;

        #pragma unroll
        for (int nt = 0; nt < 8; nt++) {
            accO[nt][0] *= cr0; accO[nt][1] *= cr0;
            accO[nt][2] *= cr1; accO[nt][3] *= cr1;
        }

        __syncwarp();
        #pragma unroll
        for (int nt = 0; nt < 8; nt++) {
            float2 p01; p01.x = f2tf32f(sacc[nt][0]); p01.y = f2tf32f(sacc[nt][1]);
            float2 p23; p23.x = f2tf32f(sacc[nt][2]); p23.y = f2tf32f(sacc[nt][3]);
            *(float2*)&Pw[lq * PPITCH + nt * 8 + 2 * lr]       = p01;
            *(float2*)&Pw[(lq + 8) * PPITCH + nt * 8 + 2 * lr] = p23;
        }
        __syncwarp();

        #pragma unroll
        for (int ks = 0; ks < 8; ks++) {
            uint32_t pa[4];
            pa[0] = __float_as_uint(Pw[lq * PPITCH + ks * 8 + lr]);
            pa[1] = __float_as_uint(Pw[(lq + 8) * PPITCH + ks * 8 + lr]);
            pa[2] = __float_as_uint(Pw[lq * PPITCH + ks * 8 + 4 + lr]);
            pa[3] = __float_as_uint(Pw[(lq + 8) * PPITCH + ks * 8 + 4 + lr]);
            #pragma unroll
            for (int nt = 0; nt < 8; nt++) {
                uint32_t bfr[2];
                bfr[0] = __float_as_uint(Vs[(ks * 8 + lr) * VPITCH + nt * 8 + lq]);
                bfr[1] = __float_as_uint(Vs[(ks * 8 + 4 + lr) * VPITCH + nt * 8 + lq]);
                mma_tf32(accO[nt], pa, bfr, accO[nt]);
            }
        }
    }

    float inv0 = 1.0f / l0r, inv1 = 1.0f / l1r;
    int row0 = qt0 + wid * 16 + lq;
    #pragma unroll
    for (int nt = 0; nt < 8; nt++) {
        float2 o0, o1;
        o0.x = f2tf32f(accO[nt][0] * inv0); o0.y = f2tf32f(accO[nt][1] * inv0);
        o1.x = f2tf32f(accO[nt][2] * inv1); o1.y = f2tf32f(accO[nt][3] * inv1);
        *(float2*)(o + base + (size_t)row0 * CC + nt * 8 + 2 * lr)       = o0;
        *(float2*)(o + base + (size_t)(row0 + 8) * CC + nt * 8 + 2 * lr) = o1;
    }
}

// ============================== launcher ==============================
extern "C" void kernel_launch(void* const* d_in, const int* in_sizes, int n_in,
                              void* d_out, int out_size) {
    (void)in_sizes; (void)n_in; (void)out_size;

    const int*   src     = (const int*)  d_in[0];
    const float* src_emb = (const float*)d_in[1];
    const float* pos_emb = (const float*)d_in[2];
    const float* ln1_w   = (const float*)d_in[3];
    const float* ln1_b   = (const float*)d_in[4];
    const float* wq      = (const float*)d_in[5];
    const float* bq      = (const float*)d_in[6];
    const float* wk      = (const float*)d_in[7];
    const float* bk      = (const float*)d_in[8];
    const float* wv      = (const float*)d_in[9];
    const float* bv      = (const float*)d_in[10];
    const float* wo      = (const float*)d_in[11];
    const float* bo      = (const float*)d_in[12];
    const float* ln2_w   = (const float*)d_in[13];
    const float* ln2_b   = (const float*)d_in[14];
    const float* w1      = (const float*)d_in[15];
    const float* b1      = (const float*)d_in[16];
    const float* w2      = (const float*)d_in[17];
    const float* b2      = (const float*)d_in[18];
    const float* lnf_w   = (const float*)d_in[19];
    const float* lnf_b   = (const float*)d_in[20];
    const float* head_w  = (const float*)d_in[21];

    float *xb, *hb, *qb, *kb, *vb, *ob, *fb, *wT;
    cudaGetSymbolAddress((void**)&xb, g_x);
    cudaGetSymbolAddress((void**)&hb, g_h);
    cudaGetSymbolAddress((void**)&qb, g_q);
    cudaGetSymbolAddress((void**)&kb, g_k);
    cudaGetSymbolAddress((void**)&vb, g_v);
    cudaGetSymbolAddress((void**)&ob, g_o);
    cudaGetSymbolAddress((void**)&fb, g_ff);
    cudaGetSymbolAddress((void**)&wT, g_wT);

    cudaFuncSetAttribute(attn_kernel, cudaFuncAttributeMaxDynamicSharedMemorySize, ATTN_SMEM);
    cudaFuncSetAttribute(mma_gemm, cudaFuncAttributeMaxDynamicSharedMemorySize, GEMM_SMEM);
    cudaFuncSetAttribute(mma_gemm_qkv, cudaFuncAttributeMaxDynamicSharedMemorySize, GEMM_SMEM);

    embed_kernel<<<MT, 256>>>(src, src_emb, pos_emb, xb);

    // grids: x = M tiles (fast), y = N tiles (slow)
    dim3 gC(MT / GBM, CC / GBN);      // (32, 8)
    dim3 gQKV(MT / GBM, 3 * CC / GBN);// (32, 24)
    dim3 gF(MT / GBM, FFD / GBN);     // (32, 32)
    dim3 gH(MT / GBM, VV / GBN);      // (32, 250)
    dim3 gA(TT / 128, HH, BSZ);       // (16, 16, 2)

    const int RB_CC = (CC * CC) / 1024;
    const int RB_FF = (CC * FFD) / 1024;
    const int RB_HD = (VV * CC) / 1024;

    for (int l = 0; l < LL; l++) {
        size_t wOff  = (size_t)l * CC * CC;
        size_t w1Off = (size_t)l * CC * FFD;
        size_t w2Off = (size_t)l * FFD * CC;

        ln_kernel<<<MT, 256>>>(xb, ln1_w + l * CC, ln1_b + l * CC, hb);

        // round q,k,v weights into wT at fixed offsets (3 proven-launches), one batched GEMM
        round_tf32_kernel<<<RB_CC, 256>>>(wq + wOff, wT);
        round_tf32_kernel<<<RB_CC, 256>>>(wk + wOff, wT + (size_t)CC * CC);
        round_tf32_kernel<<<RB_CC, 256>>>(wv + wOff, wT + (size_t)2 * CC * CC);
        mma_gemm_qkv<<<gQKV, 256, GEMM_SMEM>>>(hb, wT, bq + l * CC, bk + l * CC,
                                               bv + l * CC, qb, kb, vb);

        attn_kernel<<<gA, 256, ATTN_SMEM>>>(qb, kb, vb, ob);

        round_tf32_kernel<<<RB_CC, 256>>>(wo + wOff, wT);
        mma_gemm<<<gC, 256, GEMM_SMEM>>>(ob, wT, bo + l * CC, xb, xb, MT, CC, CC, 0, 0);

        ln_kernel<<<MT, 256>>>(xb, ln2_w + l * CC, ln2_b + l * CC, hb);

        round_tf32_kernel<<<RB_FF, 256>>>(w1 + w1Off, wT);
        mma_gemm<<<gF, 256, GEMM_SMEM>>>(hb, wT, b1 + l * FFD, nullptr, fb, MT, FFD, CC, 1, 1);
        round_tf32_kernel<<<RB_FF, 256>>>(w2 + w2Off, wT);
        mma_gemm<<<gC, 256, GEMM_SMEM>>>(fb, wT, b2 + l * CC, xb, xb, MT, CC, FFD, 0, 0);
    }

    ln_kernel<<<MT, 256>>>(xb, lnf_w, lnf_b, hb);
    round_tf32_kernel<<<RB_HD, 256>>>(head_w, wT);
    mma_gemm<<<gH, 256, GEMM_SMEM>>>(hb, wT, nullptr, nullptr, (float*)d_out, MT, VV, CC, 0, 0);
}